// round 2
// baseline (speedup 1.0000x reference)
#include <cuda_runtime.h>
#include <cuda_bf16.h>

// LightGCNConv: out = norm_dst ⊙ scatter_sum(dst, feature[src] * norm_src[src])
// feature: [N, 64] f32, src/dst: [E] i32, out: [N, 64] f32
//
// R2: precompute per-node norms (kill 17.6M redundant MUFU rsqrts that were
// co-binding scatter and dominating finalize).

#define MAX_NODES 100000
#define DFEAT 64
#define DVEC 16  // float4s per row

__device__ int   g_outdeg[MAX_NODES];
__device__ int   g_indeg[MAX_NODES];
__device__ float g_nsrc[MAX_NODES];
__device__ float g_ndst[MAX_NODES];

__global__ void zero_deg_kernel(int n) {
    int i = blockIdx.x * blockDim.x + threadIdx.x;
    if (i < n) {
        g_outdeg[i] = 0;
        g_indeg[i] = 0;
    }
}

__global__ void count_deg_kernel(const int* __restrict__ src,
                                 const int* __restrict__ dst, int E) {
    int e = blockIdx.x * blockDim.x + threadIdx.x;
    if (e < E) {
        atomicAdd(&g_outdeg[src[e]], 1);
        atomicAdd(&g_indeg[dst[e]], 1);
    }
}

__global__ void norm_kernel(int n) {
    int i = blockIdx.x * blockDim.x + threadIdx.x;
    if (i < n) {
        g_nsrc[i] = rsqrtf((float)max(g_outdeg[i], 1));
        g_ndst[i] = rsqrtf((float)max(g_indeg[i], 1));
    }
}

// 16 threads per edge; thread q owns float4 #q of the 64-float row.
__global__ void scatter_kernel(const float4* __restrict__ feat,
                               const int* __restrict__ src,
                               const int* __restrict__ dst,
                               float4* __restrict__ out, int E) {
    long long t = (long long)blockIdx.x * blockDim.x + threadIdx.x;
    int e = (int)(t >> 4);
    int q = (int)(t & 15);
    if (e >= E) return;

    int s = __ldg(&src[e]);
    int d = __ldg(&dst[e]);
    float rn = __ldg(&g_nsrc[s]);

    float4 v = __ldg(&feat[(long long)s * DVEC + q]);
    v.x *= rn; v.y *= rn; v.z *= rn; v.w *= rn;

    float4* addr = &out[(long long)d * DVEC + q];
    asm volatile("red.global.add.v4.f32 [%0], {%1, %2, %3, %4};"
                 :: "l"(addr), "f"(v.x), "f"(v.y), "f"(v.z), "f"(v.w)
                 : "memory");
}

__global__ void finalize_kernel(float4* __restrict__ out, int n) {
    int i = blockIdx.x * blockDim.x + threadIdx.x;  // over n*16 float4s
    if (i >= n * DVEC) return;
    int node = i >> 4;
    float rn = __ldg(&g_ndst[node]);
    float4 v = out[i];
    v.x *= rn; v.y *= rn; v.z *= rn; v.w *= rn;
    out[i] = v;
}

extern "C" void kernel_launch(void* const* d_in, const int* in_sizes, int n_in,
                              void* d_out, int out_size) {
    const float4* feat = (const float4*)d_in[0];
    const int*    src  = (const int*)d_in[1];
    const int*    dst  = (const int*)d_in[2];
    float4*       out  = (float4*)d_out;

    int N = in_sizes[0] / DFEAT;   // 100000
    int E = in_sizes[1];           // 1000000

    // 0) zero the accumulator (d_out is poisoned by the harness)
    cudaMemsetAsync(d_out, 0, (size_t)out_size * sizeof(float));

    // 1) zero degree scratch
    {
        int threads = 256;
        int blocks = (N + threads - 1) / threads;
        zero_deg_kernel<<<blocks, threads>>>(N);
    }

    // 2) degree counts
    {
        int threads = 256;
        int blocks = (E + threads - 1) / threads;
        count_deg_kernel<<<blocks, threads>>>(src, dst, E);
    }

    // 3) per-node norms (one rsqrt per node instead of per edge-lane)
    {
        int threads = 256;
        int blocks = (N + threads - 1) / threads;
        norm_kernel<<<blocks, threads>>>(N);
    }

    // 4) normalized gather + vector-red scatter
    {
        long long total = (long long)E * DVEC;
        int threads = 256;
        int blocks = (int)((total + threads - 1) / threads);
        scatter_kernel<<<blocks, threads>>>(feat, src, dst, out, E);
    }

    // 5) post-normalize by in-degree
    {
        int total = N * DVEC;
        int threads = 256;
        int blocks = (total + threads - 1) / threads;
        finalize_kernel<<<blocks, threads>>>(out, N);
    }
}

// round 3
// speedup vs baseline: 1.3770x; 1.3770x over previous
#include <cuda_runtime.h>
#include <cuda_bf16.h>

// LightGCNConv R3: destination-binned gather (kills the LTS atomic-rate wall).
//
// Pipeline:
//  0) memset out = 0
//  1) zero cursor/outdeg/overflow counter
//  2) bin: count outdeg; slot=atomicAdd(cursor[dst]); bucket[dst*CAP+slot]=src
//     (overflow edges -> global list)
//  3) norms: nsrc=rsqrt(max(outdeg,1)), ndst=rsqrt(max(indeg,1)) (indeg==cursor)
//  4) overflow edges: RED.v4 into out (normally zero edges)
//  5) gather: 16 lanes/node accumulate bucket msgs in regs, single write out

#define MAX_NODES 100000
#define MAX_EDGES 1000000
#define DFEAT 64
#define DVEC 16  // float4s per row
#define CAP 64   // bucket capacity per node (avg in-deg = 10)

__device__ int   g_outdeg[MAX_NODES];
__device__ int   g_cursor[MAX_NODES];          // becomes in-degree
__device__ float g_nsrc[MAX_NODES];
__device__ float g_ndst[MAX_NODES];
__device__ int   g_bucket[MAX_NODES * CAP];    // 25.6 MB scratch
__device__ int   g_ovf[MAX_EDGES];
__device__ int   g_ovf_count;

__global__ void zero_kernel(int n) {
    int i = blockIdx.x * blockDim.x + threadIdx.x;
    if (i < n) {
        g_outdeg[i] = 0;
        g_cursor[i] = 0;
    }
    if (i == 0) g_ovf_count = 0;
}

__global__ void bin_kernel(const int* __restrict__ src,
                           const int* __restrict__ dst, int E) {
    int e = blockIdx.x * blockDim.x + threadIdx.x;
    if (e >= E) return;
    int s = src[e];
    int d = dst[e];
    atomicAdd(&g_outdeg[s], 1);
    int slot = atomicAdd(&g_cursor[d], 1);
    if (slot < CAP) {
        g_bucket[d * CAP + slot] = s;
    } else {
        int pos = atomicAdd(&g_ovf_count, 1);
        g_ovf[pos] = e;
    }
}

__global__ void norm_kernel(int n) {
    int i = blockIdx.x * blockDim.x + threadIdx.x;
    if (i < n) {
        g_nsrc[i] = rsqrtf((float)max(g_outdeg[i], 1));
        g_ndst[i] = rsqrtf((float)max(g_cursor[i], 1));
    }
}

// Handles edges that overflowed the bucket (expected: none). RED into out.
__global__ void overflow_kernel(const float4* __restrict__ feat,
                                const int* __restrict__ src,
                                const int* __restrict__ dst,
                                float4* __restrict__ out) {
    int total = g_ovf_count * DVEC;
    for (int i = blockIdx.x * blockDim.x + threadIdx.x; i < total;
         i += gridDim.x * blockDim.x) {
        int e = g_ovf[i >> 4];
        int q = i & 15;
        int s = src[e];
        int d = dst[e];
        float rn = g_nsrc[s];
        float4 v = __ldg(&feat[(long long)s * DVEC + q]);
        v.x *= rn; v.y *= rn; v.z *= rn; v.w *= rn;
        float4* addr = &out[(long long)d * DVEC + q];
        asm volatile("red.global.add.v4.f32 [%0], {%1, %2, %3, %4};"
                     :: "l"(addr), "f"(v.x), "f"(v.y), "f"(v.z), "f"(v.w)
                     : "memory");
    }
}

// 16 lanes per node; lane q owns float4 #q. No atomics on the fast path.
__global__ void gather_kernel(const float4* __restrict__ feat,
                              float4* __restrict__ out, int N) {
    int t = blockIdx.x * blockDim.x + threadIdx.x;
    int node = t >> 4;
    int q = t & 15;
    if (node >= N) return;

    int deg = __ldg(&g_cursor[node]);       // broadcast across the 16 lanes
    int k = min(deg, CAP);

    float4 acc = make_float4(0.f, 0.f, 0.f, 0.f);
    const int* bkt = &g_bucket[node * CAP];

    #pragma unroll 4
    for (int i = 0; i < k; i++) {
        int s = __ldg(&bkt[i]);             // broadcast
        float rn = __ldg(&g_nsrc[s]);       // broadcast
        float4 v = __ldg(&feat[(long long)s * DVEC + q]);
        acc.x = fmaf(v.x, rn, acc.x);
        acc.y = fmaf(v.y, rn, acc.y);
        acc.z = fmaf(v.z, rn, acc.z);
        acc.w = fmaf(v.w, rn, acc.w);
    }

    float nd = __ldg(&g_ndst[node]);
    long long oidx = (long long)node * DVEC + q;
    if (deg > CAP) {                        // overflow REDs already landed in out
        float4 p = out[oidx];
        acc.x += p.x; acc.y += p.y; acc.z += p.z; acc.w += p.w;
    }
    acc.x *= nd; acc.y *= nd; acc.z *= nd; acc.w *= nd;
    out[oidx] = acc;
}

extern "C" void kernel_launch(void* const* d_in, const int* in_sizes, int n_in,
                              void* d_out, int out_size) {
    const float4* feat = (const float4*)d_in[0];
    const int*    src  = (const int*)d_in[1];
    const int*    dst  = (const int*)d_in[2];
    float4*       out  = (float4*)d_out;

    int N = in_sizes[0] / DFEAT;   // 100000
    int E = in_sizes[1];           // 1000000

    // 0) zero the accumulator (needed for the overflow RED path)
    cudaMemsetAsync(d_out, 0, (size_t)out_size * sizeof(float));

    // 1) zero scratch
    {
        int threads = 256;
        int blocks = (N + threads - 1) / threads;
        zero_kernel<<<blocks, threads>>>(N);
    }

    // 2) degree count + dst binning
    {
        int threads = 256;
        int blocks = (E + threads - 1) / threads;
        bin_kernel<<<blocks, threads>>>(src, dst, E);
    }

    // 3) per-node norms
    {
        int threads = 256;
        int blocks = (N + threads - 1) / threads;
        norm_kernel<<<blocks, threads>>>(N);
    }

    // 4) overflow edges (normally zero iterations)
    overflow_kernel<<<4, 256>>>(feat, src, dst, out);

    // 5) register-accumulated gather, single write per node
    {
        long long total = (long long)N * DVEC;
        int threads = 256;
        int blocks = (int)((total + threads - 1) / threads);
        gather_kernel<<<blocks, threads>>>(feat, out, N);
    }
}

// round 4
// speedup vs baseline: 1.6362x; 1.1882x over previous
#include <cuda_runtime.h>
#include <cuda_bf16.h>

// LightGCNConv R4: destination-binned register gather, zero overhead passes.
//
// Pipeline (4 launches, no memset):
//  1) zero cursor/outdeg/overflow counter
//  2) bin: count outdeg; slot=atomicAdd(cursor[dst]); bucket[dst*CAP+slot]=src
//     overflow edges (deg>CAP, ~never) -> (src,dst) pair list
//  3) norms: nsrc=rsqrt(max(outdeg,1)), ndst=rsqrt(max(indeg,1))
//  4) gather: 16 lanes/node accumulate bucket in regs; overflowing nodes also
//     scan the tiny pair list inline. Exactly one write per output element.

#define MAX_NODES 100000
#define MAX_EDGES 1000000
#define DFEAT 64
#define DVEC 16  // float4s per row
#define CAP 64   // bucket capacity per node (avg in-deg = 10, Poisson tail << 64)

__device__ int   g_outdeg[MAX_NODES];
__device__ int   g_cursor[MAX_NODES];          // becomes in-degree
__device__ float g_nsrc[MAX_NODES];
__device__ float g_ndst[MAX_NODES];
__device__ int   g_bucket[MAX_NODES * CAP];    // 25.6 MB scratch
__device__ int   g_ovf_src[4096];
__device__ int   g_ovf_dst[4096];
__device__ int   g_ovf_count;

__global__ void zero_kernel(int n) {
    int i = blockIdx.x * blockDim.x + threadIdx.x;
    if (i < n) {
        g_outdeg[i] = 0;
        g_cursor[i] = 0;
    }
    if (i == 0) g_ovf_count = 0;
}

__global__ void bin_kernel(const int* __restrict__ src,
                           const int* __restrict__ dst, int E) {
    int e = blockIdx.x * blockDim.x + threadIdx.x;
    if (e >= E) return;
    int s = src[e];
    int d = dst[e];
    atomicAdd(&g_outdeg[s], 1);
    int slot = atomicAdd(&g_cursor[d], 1);
    if (slot < CAP) {
        g_bucket[d * CAP + slot] = s;
    } else {
        int pos = atomicAdd(&g_ovf_count, 1);
        if (pos < 4096) {
            g_ovf_src[pos] = s;
            g_ovf_dst[pos] = d;
        }
    }
}

__global__ void norm_kernel(int n) {
    int i = blockIdx.x * blockDim.x + threadIdx.x;
    if (i < n) {
        g_nsrc[i] = rsqrtf((float)max(g_outdeg[i], 1));
        g_ndst[i] = rsqrtf((float)max(g_cursor[i], 1));
    }
}

// 16 lanes per node; lane q owns float4 #q. No atomics, single write per elem.
__global__ void gather_kernel(const float4* __restrict__ feat,
                              float4* __restrict__ out, int N) {
    int t = blockIdx.x * blockDim.x + threadIdx.x;
    int node = t >> 4;
    int q = t & 15;
    if (node >= N) return;

    int deg = __ldg(&g_cursor[node]);       // broadcast across the 16 lanes
    int k = min(deg, CAP);

    float4 acc = make_float4(0.f, 0.f, 0.f, 0.f);
    const int* bkt = &g_bucket[node * CAP];

    #pragma unroll 4
    for (int i = 0; i < k; i++) {
        int s = __ldg(&bkt[i]);             // broadcast
        float rn = __ldg(&g_nsrc[s]);       // broadcast
        float4 v = __ldg(&feat[(long long)s * DVEC + q]);
        acc.x = fmaf(v.x, rn, acc.x);
        acc.y = fmaf(v.y, rn, acc.y);
        acc.z = fmaf(v.z, rn, acc.z);
        acc.w = fmaf(v.w, rn, acc.w);
    }

    // Slow path: edges that overflowed this node's bucket (expected: none).
    if (deg > CAP) {
        int ovfn = min(g_ovf_count, 4096);
        for (int j = 0; j < ovfn; j++) {
            if (g_ovf_dst[j] == node) {
                int s = g_ovf_src[j];
                float rn = __ldg(&g_nsrc[s]);
                float4 v = __ldg(&feat[(long long)s * DVEC + q]);
                acc.x = fmaf(v.x, rn, acc.x);
                acc.y = fmaf(v.y, rn, acc.y);
                acc.z = fmaf(v.z, rn, acc.z);
                acc.w = fmaf(v.w, rn, acc.w);
            }
        }
    }

    float nd = __ldg(&g_ndst[node]);
    acc.x *= nd; acc.y *= nd; acc.z *= nd; acc.w *= nd;
    out[(long long)node * DVEC + q] = acc;
}

extern "C" void kernel_launch(void* const* d_in, const int* in_sizes, int n_in,
                              void* d_out, int out_size) {
    const float4* feat = (const float4*)d_in[0];
    const int*    src  = (const int*)d_in[1];
    const int*    dst  = (const int*)d_in[2];
    float4*       out  = (float4*)d_out;

    int N = in_sizes[0] / DFEAT;   // 100000
    int E = in_sizes[1];           // 1000000

    // 1) zero scratch
    {
        int threads = 256;
        int blocks = (N + threads - 1) / threads;
        zero_kernel<<<blocks, threads>>>(N);
    }

    // 2) degree count + dst binning
    {
        int threads = 256;
        int blocks = (E + threads - 1) / threads;
        bin_kernel<<<blocks, threads>>>(src, dst, E);
    }

    // 3) per-node norms
    {
        int threads = 256;
        int blocks = (N + threads - 1) / threads;
        norm_kernel<<<blocks, threads>>>(N);
    }

    // 4) register-accumulated gather, single write per output element
    {
        long long total = (long long)N * DVEC;
        int threads = 256;
        int blocks = (int)((total + threads - 1) / threads);
        gather_kernel<<<blocks, threads>>>(feat, out, N);
    }
}